// round 1
// baseline (speedup 1.0000x reference)
#include <cuda_runtime.h>
#include <cstdint>

#define N_NODES 16384
#define N_EDGES 131072
#define ED      32
#define NGRAPH  128
#define MAXF    1024
#define NEG_SLOPE 0.2f

// ---------------- scratch (static device memory; no allocs) ----------------
__device__ float g_hA[(size_t)N_NODES * MAXF];
__device__ float g_hB[(size_t)N_NODES * MAXF];
__device__ float g_xl[(size_t)N_NODES * MAXF];
__device__ float g_xr[(size_t)N_NODES * MAXF];
__device__ float g_eaWe[(size_t)N_EDGES * MAXF];   // 512 MB
__device__ float g_loopWe[(size_t)N_NODES * MAXF];
__device__ float g_loop_attr[N_NODES * ED];
__device__ int   g_deg[N_NODES];
__device__ int   g_off[N_NODES + 1];
__device__ int   g_cur[N_NODES];
__device__ int   g_ssrc[N_EDGES];
__device__ int   g_sdst[N_EDGES];
__device__ int   g_seid[N_EDGES];
__device__ float g_elog[N_EDGES];
__device__ float g_eself[N_NODES];
__device__ float g_pool[NGRAPH * 256];
__device__ int   g_gcnt[NGRAPH];

// ---------------- utility kernels ----------------
__global__ void zero_f(float* p, int n) {
    int i = blockIdx.x * blockDim.x + threadIdx.x;
    if (i < n) p[i] = 0.0f;
}
__global__ void zero_i(int* p, int n) {
    int i = blockIdx.x * blockDim.x + threadIdx.x;
    if (i < n) p[i] = 0;
}

__global__ void count_deg(const int* __restrict__ dst) {
    int i = blockIdx.x * blockDim.x + threadIdx.x;
    if (i < N_EDGES) atomicAdd(&g_deg[dst[i]], 1);
}

__global__ void acc_loop_attr(const int* __restrict__ dst, const float* __restrict__ ea) {
    int i = blockIdx.x * blockDim.x + threadIdx.x;
    if (i >= N_EDGES * ED) return;
    int j = i >> 5, d = i & 31;
    atomicAdd(&g_loop_attr[dst[j] * ED + d], ea[(size_t)j * ED + d]);
}

__global__ void div_loop_attr() {
    int i = blockIdx.x * blockDim.x + threadIdx.x;
    if (i >= N_NODES * ED) return;
    int n = i >> 5;
    float dg = fmaxf((float)g_deg[n], 1.0f);
    g_loop_attr[i] /= dg;
}

// exclusive scan of g_deg[16384] -> g_off, single block of 1024 threads
__global__ void scan_deg() {
    __shared__ int part[1024];
    int tid = threadIdx.x;
    int base = tid * 16;
    int loc[16];
    int s = 0;
#pragma unroll
    for (int k = 0; k < 16; k++) { loc[k] = s; s += g_deg[base + k]; }
    part[tid] = s;
    __syncthreads();
    for (int d = 1; d < 1024; d <<= 1) {
        int v = (tid >= d) ? part[tid - d] : 0;
        __syncthreads();
        part[tid] += v;
        __syncthreads();
    }
    int pre = (tid == 0) ? 0 : part[tid - 1];
#pragma unroll
    for (int k = 0; k < 16; k++) g_off[base + k] = pre + loc[k];
    if (tid == 1023) g_off[N_NODES] = part[1023];
}

__global__ void scatter_edges(const int* __restrict__ src, const int* __restrict__ dst) {
    int i = blockIdx.x * blockDim.x + threadIdx.x;
    if (i >= N_EDGES) return;
    int d = dst[i];
    int p = g_off[d] + atomicAdd(&g_cur[d], 1);
    g_ssrc[p] = src[i];
    g_sdst[p] = d;
    g_seid[p] = i;
}

// ---------------- SGEMM: C[M,N] = A[M,K] @ B[K,N] (+bias) ----------------
// BM=BN=128, BK=16, 256 threads, 8x8 per thread. M%128==0, N%128==0, K%16==0.
__global__ __launch_bounds__(256) void sgemm_bias(
    const float* __restrict__ A, const float* __restrict__ B,
    const float* __restrict__ bias, float* __restrict__ C,
    int M, int N, int K) {
    __shared__ __align__(16) float As[16][128];
    __shared__ __align__(16) float Bs[16][128];
    int tid = threadIdx.x;
    int tx = tid & 15, ty = tid >> 4;
    int row0 = blockIdx.y * 128, col0 = blockIdx.x * 128;
    float acc[8][8] = {};
    for (int k0 = 0; k0 < K; k0 += 16) {
#pragma unroll
        for (int q = 0; q < 2; q++) {
            int f4 = tid + q * 256;
            int r = f4 >> 2, c4 = f4 & 3;
            float4 va = *reinterpret_cast<const float4*>(&A[(size_t)(row0 + r) * K + k0 + c4 * 4]);
            As[c4 * 4 + 0][r] = va.x;
            As[c4 * 4 + 1][r] = va.y;
            As[c4 * 4 + 2][r] = va.z;
            As[c4 * 4 + 3][r] = va.w;
            int rb = f4 >> 5, cb = f4 & 31;
            *reinterpret_cast<float4*>(&Bs[rb][cb * 4]) =
                *reinterpret_cast<const float4*>(&B[(size_t)(k0 + rb) * N + col0 + cb * 4]);
        }
        __syncthreads();
#pragma unroll
        for (int kk = 0; kk < 16; kk++) {
            float a[8], b[8];
            *reinterpret_cast<float4*>(a)     = *reinterpret_cast<float4*>(&As[kk][ty * 8]);
            *reinterpret_cast<float4*>(a + 4) = *reinterpret_cast<float4*>(&As[kk][ty * 8 + 4]);
            *reinterpret_cast<float4*>(b)     = *reinterpret_cast<float4*>(&Bs[kk][tx * 8]);
            *reinterpret_cast<float4*>(b + 4) = *reinterpret_cast<float4*>(&Bs[kk][tx * 8 + 4]);
#pragma unroll
            for (int i = 0; i < 8; i++)
#pragma unroll
                for (int j = 0; j < 8; j++) acc[i][j] += a[i] * b[j];
        }
        __syncthreads();
    }
    float bv[8];
#pragma unroll
    for (int j = 0; j < 8; j++) bv[j] = bias ? bias[col0 + tx * 8 + j] : 0.0f;
#pragma unroll
    for (int i = 0; i < 8; i++) {
        size_t r = row0 + ty * 8 + i;
#pragma unroll
        for (int j = 0; j < 8; j++) {
            C[r * N + col0 + tx * 8 + j] = acc[i][j] + bv[j];
        }
    }
}

// ---------------- attention logits ----------------
// one warp per sorted edge position
__global__ void edge_logit(const float* __restrict__ att, int F) {
    int w = (blockIdx.x * blockDim.x + threadIdx.x) >> 5;
    int lane = threadIdx.x & 31;
    if (w >= N_EDGES) return;
    int s = g_ssrc[w], d = g_sdst[w], eid = g_seid[w];
    const float* xl = &g_xl[(size_t)s * F];
    const float* xr = &g_xr[(size_t)d * F];
    const float* ew = &g_eaWe[(size_t)eid * F];
    float acc = 0.0f;
    for (int f = lane; f < F; f += 32) {
        float v = xl[f] + xr[f] + ew[f];
        v = (v > 0.0f) ? v : NEG_SLOPE * v;
        acc += v * att[f];
    }
#pragma unroll
    for (int o = 16; o; o >>= 1) acc += __shfl_xor_sync(0xffffffffu, acc, o);
    if (lane == 0) g_elog[w] = acc;
}

__global__ void self_logit(const float* __restrict__ att, int F) {
    int n = (blockIdx.x * blockDim.x + threadIdx.x) >> 5;
    int lane = threadIdx.x & 31;
    if (n >= N_NODES) return;
    const float* xl = &g_xl[(size_t)n * F];
    const float* xr = &g_xr[(size_t)n * F];
    const float* ew = &g_loopWe[(size_t)n * F];
    float acc = 0.0f;
    for (int f = lane; f < F; f += 32) {
        float v = xl[f] + xr[f] + ew[f];
        v = (v > 0.0f) ? v : NEG_SLOPE * v;
        acc += v * att[f];
    }
#pragma unroll
    for (int o = 16; o; o >>= 1) acc += __shfl_xor_sync(0xffffffffu, acc, o);
    if (lane == 0) g_eself[n] = acc;
}

// ---------------- per-destination softmax + aggregate (+bias+relu) ----------------
__global__ __launch_bounds__(256) void aggregate(const float* __restrict__ bc,
                                                 float* __restrict__ out, int F) {
    int n = blockIdx.x;
    int tid = threadIdx.x;
    int off = g_off[n];
    int deg = g_off[n + 1] - off;
    __shared__ float red[256];
    __shared__ float s_alpha[128];
    __shared__ int s_src[128];

    float eself = g_eself[n];
    float m = eself;
    for (int j = tid; j < deg; j += 256) m = fmaxf(m, g_elog[off + j]);
    red[tid] = m;
    __syncthreads();
    for (int s = 128; s > 0; s >>= 1) {
        if (tid < s) red[tid] = fmaxf(red[tid], red[tid + s]);
        __syncthreads();
    }
    m = red[0];
    __syncthreads();
    float ds = 0.0f;
    for (int j = tid; j < deg; j += 256) ds += __expf(g_elog[off + j] - m);
    red[tid] = ds;
    __syncthreads();
    for (int s = 128; s > 0; s >>= 1) {
        if (tid < s) red[tid] += red[tid + s];
        __syncthreads();
    }
    float eself_x = __expf(eself - m);
    float inv = 1.0f / (red[0] + eself_x);
    __syncthreads();

    int nr = F >> 8;  // F in {256,512,1024}
    float acc[4];
    const float* xln = &g_xl[(size_t)n * F];
    float aself = eself_x * inv;
    for (int r = 0; r < nr; r++) acc[r] = aself * xln[tid + (r << 8)];

    for (int c0 = 0; c0 < deg; c0 += 128) {
        int cnt = min(128, deg - c0);
        if (tid < cnt) {
            s_alpha[tid] = __expf(g_elog[off + c0 + tid] - m) * inv;
            s_src[tid] = g_ssrc[off + c0 + tid];
        }
        __syncthreads();
        for (int j = 0; j < cnt; j++) {
            const float* xs = &g_xl[(size_t)s_src[j] * F];
            float a = s_alpha[j];
            for (int r = 0; r < nr; r++) acc[r] += a * xs[tid + (r << 8)];
        }
        __syncthreads();
    }
    for (int r = 0; r < nr; r++) {
        int f = tid + (r << 8);
        out[(size_t)n * F + f] = fmaxf(acc[r] + bc[f], 0.0f);
    }
}

// ---------------- pooling ----------------
__global__ void pool_acc(const float* __restrict__ h, const int* __restrict__ batch) {
    int i = blockIdx.x * blockDim.x + threadIdx.x;
    if (i >= N_NODES * 256) return;
    int n = i >> 8, f = i & 255;
    atomicAdd(&g_pool[batch[n] * 256 + f], h[i]);
}
__global__ void cnt_acc(const int* __restrict__ batch) {
    int i = blockIdx.x * blockDim.x + threadIdx.x;
    if (i < N_NODES) atomicAdd(&g_gcnt[batch[i]], 1);
}

// ---------------- MLP head (single block) ----------------
__global__ __launch_bounds__(256) void mlp_head(
    const float* __restrict__ fc1w, const float* __restrict__ fc1b,
    const float* __restrict__ bng, const float* __restrict__ bnb,
    const float* __restrict__ fc2w, const float* __restrict__ fc2b,
    float* __restrict__ out) {
    __shared__ float z[NGRAPH * 64];
    __shared__ float mu[64], iv[64];
    int tid = threadIdx.x;
    for (int i = tid; i < NGRAPH * 64; i += 256) {
        int g = i >> 6, o = i & 63;
        float cnt = fmaxf((float)g_gcnt[g], 1.0f);
        float s = 0.0f;
        for (int k = 0; k < 256; k++) s += g_pool[g * 256 + k] * fc1w[k * 64 + o];
        z[i] = s / cnt + fc1b[o];
    }
    __syncthreads();
    if (tid < 64) {
        float s = 0.0f, s2 = 0.0f;
        for (int g = 0; g < NGRAPH; g++) {
            float v = z[g * 64 + tid];
            s += v; s2 += v * v;
        }
        float mean = s / (float)NGRAPH;
        float var = s2 / (float)NGRAPH - mean * mean;
        mu[tid] = mean;
        iv[tid] = rsqrtf(var + 1e-5f);
    }
    __syncthreads();
    for (int i = tid; i < NGRAPH * 64; i += 256) {
        int o = i & 63;
        float v = (z[i] - mu[o]) * iv[o] * bng[o] + bnb[o];
        z[i] = fmaxf(v, 0.0f);
    }
    __syncthreads();
    if (tid < NGRAPH) {
        float s = 0.0f;
        for (int o = 0; o < 64; o++) s += z[tid * 64 + o] * fc2w[o];
        out[tid] = s + fc2b[0];
    }
}

// ---------------- host-side layer driver ----------------
static void run_layer(const float* hin, int Fin, int Fout, float* hout,
                      const float* Wl, const float* bl,
                      const float* Wr, const float* br,
                      const float* We, const float* att, const float* bc,
                      const float* edge_attr,
                      float* d_xl, float* d_xr, float* d_eaWe, float* d_loopWe,
                      float* d_loop_attr) {
    dim3 t(256);
    // xl = hin@Wl + bl ; xr = hin@Wr + br
    {
        dim3 g(Fout / 128, N_NODES / 128);
        sgemm_bias<<<g, t>>>(hin, Wl, bl, d_xl, N_NODES, Fout, Fin);
        sgemm_bias<<<g, t>>>(hin, Wr, br, d_xr, N_NODES, Fout, Fin);
    }
    // eaWe = edge_attr @ We ; loopWe = loop_attr @ We
    {
        dim3 g(Fout / 128, N_EDGES / 128);
        sgemm_bias<<<g, t>>>(edge_attr, We, nullptr, d_eaWe, N_EDGES, Fout, ED);
        dim3 g2(Fout / 128, N_NODES / 128);
        sgemm_bias<<<g2, t>>>(d_loop_attr, We, nullptr, d_loopWe, N_NODES, Fout, ED);
    }
    edge_logit<<<(N_EDGES * 32 + 255) / 256, 256>>>(att, Fout);
    self_logit<<<(N_NODES * 32 + 255) / 256, 256>>>(att, Fout);
    aggregate<<<N_NODES, 256>>>(bc, hout, Fout);
}

extern "C" void kernel_launch(void* const* d_in, const int* in_sizes, int n_in,
                              void* d_out, int out_size) {
    const float* x         = (const float*)d_in[0];
    const int*   ei        = (const int*)d_in[1];
    const float* edge_attr = (const float*)d_in[2];
    const int*   batch     = (const int*)d_in[3];

    const float* Wl[3], *bl[3], *Wr[3], *br[3], *We[3], *att[3], *bc[3];
    for (int l = 0; l < 3; l++) {
        int b = 4 + l * 7;
        Wl[l]  = (const float*)d_in[b + 0];
        bl[l]  = (const float*)d_in[b + 1];
        Wr[l]  = (const float*)d_in[b + 2];
        br[l]  = (const float*)d_in[b + 3];
        We[l]  = (const float*)d_in[b + 4];
        att[l] = (const float*)d_in[b + 5];
        bc[l]  = (const float*)d_in[b + 6];
    }
    const float* fc1w = (const float*)d_in[25];
    const float* fc1b = (const float*)d_in[26];
    const float* bng  = (const float*)d_in[27];
    const float* bnb  = (const float*)d_in[28];
    const float* fc2w = (const float*)d_in[29];
    const float* fc2b = (const float*)d_in[30];
    float* out = (float*)d_out;

    const int* src = ei;
    const int* dst = ei + N_EDGES;

    // device-symbol addresses (host-visible only via cudaGetSymbolAddress)
    float *d_hA, *d_hB, *d_xl, *d_xr, *d_eaWe, *d_loopWe, *d_loop_attr, *d_pool;
    int *d_deg, *d_cur, *d_gcnt;
    cudaGetSymbolAddress((void**)&d_hA, g_hA);
    cudaGetSymbolAddress((void**)&d_hB, g_hB);
    cudaGetSymbolAddress((void**)&d_xl, g_xl);
    cudaGetSymbolAddress((void**)&d_xr, g_xr);
    cudaGetSymbolAddress((void**)&d_eaWe, g_eaWe);
    cudaGetSymbolAddress((void**)&d_loopWe, g_loopWe);
    cudaGetSymbolAddress((void**)&d_loop_attr, g_loop_attr);
    cudaGetSymbolAddress((void**)&d_pool, g_pool);
    cudaGetSymbolAddress((void**)&d_deg, g_deg);
    cudaGetSymbolAddress((void**)&d_cur, g_cur);
    cudaGetSymbolAddress((void**)&d_gcnt, g_gcnt);

    // ---- graph preprocessing (structure fixed, recomputed each call: deterministic) ----
    zero_i<<<(N_NODES + 255) / 256, 256>>>(d_deg, N_NODES);
    zero_i<<<(N_NODES + 255) / 256, 256>>>(d_cur, N_NODES);
    zero_i<<<(NGRAPH + 255) / 256, 256>>>(d_gcnt, NGRAPH);
    zero_f<<<(N_NODES * ED + 255) / 256, 256>>>(d_loop_attr, N_NODES * ED);
    zero_f<<<(NGRAPH * 256 + 255) / 256, 256>>>(d_pool, NGRAPH * 256);

    count_deg<<<(N_EDGES + 255) / 256, 256>>>(dst);
    acc_loop_attr<<<(N_EDGES * ED + 255) / 256, 256>>>(dst, edge_attr);
    scan_deg<<<1, 1024>>>();
    scatter_edges<<<(N_EDGES + 255) / 256, 256>>>(src, dst);
    div_loop_attr<<<(N_NODES * ED + 255) / 256, 256>>>();

    // ---- 3 GATv2 layers ----
    run_layer(x,    256,  512, d_hA, Wl[0], bl[0], Wr[0], br[0], We[0], att[0], bc[0],
              edge_attr, d_xl, d_xr, d_eaWe, d_loopWe, d_loop_attr);
    run_layer(d_hA, 512, 1024, d_hB, Wl[1], bl[1], Wr[1], br[1], We[1], att[1], bc[1],
              edge_attr, d_xl, d_xr, d_eaWe, d_loopWe, d_loop_attr);
    run_layer(d_hB, 1024, 256, d_hA, Wl[2], bl[2], Wr[2], br[2], We[2], att[2], bc[2],
              edge_attr, d_xl, d_xr, d_eaWe, d_loopWe, d_loop_attr);

    // ---- pool + MLP head ----
    cnt_acc<<<(N_NODES + 255) / 256, 256>>>(batch);
    pool_acc<<<(N_NODES * 256 + 255) / 256, 256>>>(d_hA, batch);
    mlp_head<<<1, 256>>>(fc1w, fc1b, bng, bnb, fc2w, fc2b, out);
}

// round 3
// speedup vs baseline: 1.8406x; 1.8406x over previous
#include <cuda_runtime.h>
#include <cuda_fp16.h>
#include <mma.h>
#include <cstdint>

using namespace nvcuda;

#define N_NODES 16384
#define N_EDGES 131072
#define ED      32
#define NGRAPH  128
#define MAXF    1024
#define NEG_SLOPE 0.2f

// ---------------- scratch (static device memory; no allocs) ----------------
__device__ float g_hA[(size_t)N_NODES * MAXF];
__device__ float g_hB[(size_t)N_NODES * MAXF];
__device__ float g_xl[(size_t)N_NODES * MAXF];
__device__ float g_xr[(size_t)N_NODES * MAXF];
__device__ float g_eaWe[(size_t)N_EDGES * MAXF];   // 512 MB
__device__ float g_loopWe[(size_t)N_NODES * MAXF];
__device__ float g_loop_attr[N_NODES * ED];
__device__ int   g_deg[N_NODES];
__device__ int   g_off[N_NODES + 1];
__device__ int   g_cur[N_NODES];
__device__ int   g_ssrc[N_EDGES];
__device__ int   g_sdst[N_EDGES];
__device__ int   g_seid[N_EDGES];
__device__ float g_elog[N_EDGES];
__device__ float g_eself[N_NODES];
__device__ float g_pool[NGRAPH * 256];
__device__ int   g_gcnt[NGRAPH];

// ---------------- utility kernels ----------------
__global__ void zero_f(float* p, int n) {
    int i = blockIdx.x * blockDim.x + threadIdx.x;
    if (i < n) p[i] = 0.0f;
}
__global__ void zero_i(int* p, int n) {
    int i = blockIdx.x * blockDim.x + threadIdx.x;
    if (i < n) p[i] = 0;
}

__global__ void count_deg(const int* __restrict__ dst) {
    int i = blockIdx.x * blockDim.x + threadIdx.x;
    if (i < N_EDGES) atomicAdd(&g_deg[dst[i]], 1);
}

__global__ void acc_loop_attr(const int* __restrict__ dst, const float* __restrict__ ea) {
    int i = blockIdx.x * blockDim.x + threadIdx.x;
    if (i >= N_EDGES * ED) return;
    int j = i >> 5, d = i & 31;
    atomicAdd(&g_loop_attr[dst[j] * ED + d], ea[(size_t)j * ED + d]);
}

__global__ void div_loop_attr() {
    int i = blockIdx.x * blockDim.x + threadIdx.x;
    if (i >= N_NODES * ED) return;
    int n = i >> 5;
    float dg = fmaxf((float)g_deg[n], 1.0f);
    g_loop_attr[i] /= dg;
}

// exclusive scan of g_deg[16384] -> g_off, single block of 1024 threads
__global__ void scan_deg() {
    __shared__ int part[1024];
    int tid = threadIdx.x;
    int base = tid * 16;
    int loc[16];
    int s = 0;
#pragma unroll
    for (int k = 0; k < 16; k++) { loc[k] = s; s += g_deg[base + k]; }
    part[tid] = s;
    __syncthreads();
    for (int d = 1; d < 1024; d <<= 1) {
        int v = (tid >= d) ? part[tid - d] : 0;
        __syncthreads();
        part[tid] += v;
        __syncthreads();
    }
    int pre = (tid == 0) ? 0 : part[tid - 1];
#pragma unroll
    for (int k = 0; k < 16; k++) g_off[base + k] = pre + loc[k];
    if (tid == 1023) g_off[N_NODES] = part[1023];
}

__global__ void scatter_edges(const int* __restrict__ src, const int* __restrict__ dst) {
    int i = blockIdx.x * blockDim.x + threadIdx.x;
    if (i >= N_EDGES) return;
    int d = dst[i];
    int p = g_off[d] + atomicAdd(&g_cur[d], 1);
    g_ssrc[p] = src[i];
    g_sdst[p] = d;
    g_seid[p] = i;
}

// ------- fp16x2-split tensor-core GEMM: C[M,N] = A[M,K] @ B[K,N] (+bias) -------
// Each fp32 value split v = hi + lo (fp16 each, 22 effective mantissa bits).
// C = A_hi*B_hi + A_hi*B_lo + A_lo*B_hi, fp32 accumulators.
// BM=BN=128, BK=32, 256 threads = 8 warps (2x4), warp computes 64x32 (4x2 frags).
// Requires M%128==0, N%128==0, K%32==0.
__global__ __launch_bounds__(256) void gemm_fp16x2_bias(
    const float* __restrict__ A, const float* __restrict__ B,
    const float* __restrict__ bias, float* __restrict__ C,
    int M, int N, int K) {
    constexpr int BM = 128, BN = 128, BK = 32;
    constexpr int LDA = BK + 8;   // 40 halves (80B, 16B-multiple)
    constexpr int LDB = BN + 8;   // 136 halves (272B)
    __shared__ __align__(16) __half As[2][BM * LDA];   // 2 x 10240 B
    __shared__ __align__(16) __half Bs[2][BK * LDB];   // 2 x 8704 B

    int tid = threadIdx.x;
    int warp = tid >> 5, lane = tid & 31;
    int wr = warp >> 2;   // 0..1
    int wc = warp & 3;    // 0..3
    int row0 = blockIdx.y * BM, col0 = blockIdx.x * BN;

    wmma::fragment<wmma::accumulator, 16, 16, 16, float> cf[4][2];
#pragma unroll
    for (int r = 0; r < 4; r++)
#pragma unroll
        for (int c = 0; c < 2; c++) wmma::fill_fragment(cf[r][c], 0.0f);

    for (int k0 = 0; k0 < K; k0 += BK) {
        // load + split A tile 128x32 (1024 float4s over 256 threads)
#pragma unroll
        for (int q = 0; q < 4; q++) {
            int lin = tid + q * 256;
            int r = lin >> 3, c4 = lin & 7;
            float4 v = *reinterpret_cast<const float4*>(&A[(size_t)(row0 + r) * K + k0 + c4 * 4]);
            float vv[4] = {v.x, v.y, v.z, v.w};
            int base = r * LDA + c4 * 4;
#pragma unroll
            for (int i = 0; i < 4; i++) {
                __half h = __float2half_rn(vv[i]);
                As[0][base + i] = h;
                As[1][base + i] = __float2half_rn(vv[i] - __half2float(h));
            }
        }
        // load + split B tile 32x128
#pragma unroll
        for (int q = 0; q < 4; q++) {
            int lin = tid + q * 256;
            int r = lin >> 5, c4 = lin & 31;
            float4 v = *reinterpret_cast<const float4*>(&B[(size_t)(k0 + r) * N + col0 + c4 * 4]);
            float vv[4] = {v.x, v.y, v.z, v.w};
            int base = r * LDB + c4 * 4;
#pragma unroll
            for (int i = 0; i < 4; i++) {
                __half h = __float2half_rn(vv[i]);
                Bs[0][base + i] = h;
                Bs[1][base + i] = __float2half_rn(vv[i] - __half2float(h));
            }
        }
        __syncthreads();
#pragma unroll
        for (int ks = 0; ks < BK / 16; ks++) {
            wmma::fragment<wmma::matrix_a, 16, 16, 16, __half, wmma::row_major> ah[4], al[4];
            wmma::fragment<wmma::matrix_b, 16, 16, 16, __half, wmma::row_major> bh[2], bl[2];
#pragma unroll
            for (int r = 0; r < 4; r++) {
                int aoff = (wr * 64 + r * 16) * LDA + ks * 16;
                wmma::load_matrix_sync(ah[r], &As[0][aoff], LDA);
                wmma::load_matrix_sync(al[r], &As[1][aoff], LDA);
            }
#pragma unroll
            for (int c = 0; c < 2; c++) {
                int boff = (ks * 16) * LDB + wc * 32 + c * 16;
                wmma::load_matrix_sync(bh[c], &Bs[0][boff], LDB);
                wmma::load_matrix_sync(bl[c], &Bs[1][boff], LDB);
            }
#pragma unroll
            for (int r = 0; r < 4; r++)
#pragma unroll
                for (int c = 0; c < 2; c++) {
                    wmma::mma_sync(cf[r][c], ah[r], bl[c], cf[r][c]);
                    wmma::mma_sync(cf[r][c], al[r], bh[c], cf[r][c]);
                    wmma::mma_sync(cf[r][c], ah[r], bh[c], cf[r][c]);
                }
        }
        __syncthreads();
    }

    // epilogue: per-warp smem staging (aliases As, safe after final sync),
    // add bias, vectorized fp32 store
    float* Ep = reinterpret_cast<float*>(&As[0][0]) + warp * 16 * 20;
    int erow = lane >> 1;            // 16 rows, 2 lanes each
    int ecol = (lane & 1) * 8;       // 8 contiguous floats per lane
#pragma unroll
    for (int r = 0; r < 4; r++) {
#pragma unroll
        for (int c = 0; c < 2; c++) {
            wmma::store_matrix_sync(Ep, cf[r][c], 20, wmma::mem_row_major);
            __syncwarp();
            int rr = row0 + wr * 64 + r * 16 + erow;
            int cc = col0 + wc * 32 + c * 16 + ecol;
            float4 v0 = *reinterpret_cast<float4*>(&Ep[erow * 20 + ecol]);
            float4 v1 = *reinterpret_cast<float4*>(&Ep[erow * 20 + ecol + 4]);
            if (bias) {
                float4 b0 = *reinterpret_cast<const float4*>(&bias[cc]);
                float4 b1 = *reinterpret_cast<const float4*>(&bias[cc + 4]);
                v0.x += b0.x; v0.y += b0.y; v0.z += b0.z; v0.w += b0.w;
                v1.x += b1.x; v1.y += b1.y; v1.z += b1.z; v1.w += b1.w;
            }
            *reinterpret_cast<float4*>(&C[(size_t)rr * N + cc])     = v0;
            *reinterpret_cast<float4*>(&C[(size_t)rr * N + cc + 4]) = v1;
            __syncwarp();
        }
    }
}

// ---------------- attention logits ----------------
// one warp per sorted edge position
__global__ void edge_logit(const float* __restrict__ att, int F) {
    int w = (blockIdx.x * blockDim.x + threadIdx.x) >> 5;
    int lane = threadIdx.x & 31;
    if (w >= N_EDGES) return;
    int s = g_ssrc[w], d = g_sdst[w], eid = g_seid[w];
    const float* xl = &g_xl[(size_t)s * F];
    const float* xr = &g_xr[(size_t)d * F];
    const float* ew = &g_eaWe[(size_t)eid * F];
    float acc = 0.0f;
    for (int f = lane; f < F; f += 32) {
        float v = xl[f] + xr[f] + ew[f];
        v = (v > 0.0f) ? v : NEG_SLOPE * v;
        acc += v * att[f];
    }
#pragma unroll
    for (int o = 16; o; o >>= 1) acc += __shfl_xor_sync(0xffffffffu, acc, o);
    if (lane == 0) g_elog[w] = acc;
}

__global__ void self_logit(const float* __restrict__ att, int F) {
    int n = (blockIdx.x * blockDim.x + threadIdx.x) >> 5;
    int lane = threadIdx.x & 31;
    if (n >= N_NODES) return;
    const float* xl = &g_xl[(size_t)n * F];
    const float* xr = &g_xr[(size_t)n * F];
    const float* ew = &g_loopWe[(size_t)n * F];
    float acc = 0.0f;
    for (int f = lane; f < F; f += 32) {
        float v = xl[f] + xr[f] + ew[f];
        v = (v > 0.0f) ? v : NEG_SLOPE * v;
        acc += v * att[f];
    }
#pragma unroll
    for (int o = 16; o; o >>= 1) acc += __shfl_xor_sync(0xffffffffu, acc, o);
    if (lane == 0) g_eself[n] = acc;
}

// ---------------- per-destination softmax + aggregate (+bias+relu) ----------------
__global__ __launch_bounds__(256) void aggregate(const float* __restrict__ bc,
                                                 float* __restrict__ out, int F) {
    int n = blockIdx.x;
    int tid = threadIdx.x;
    int off = g_off[n];
    int deg = g_off[n + 1] - off;
    __shared__ float red[256];
    __shared__ float s_alpha[128];
    __shared__ int s_src[128];

    float eself = g_eself[n];
    float m = eself;
    for (int j = tid; j < deg; j += 256) m = fmaxf(m, g_elog[off + j]);
    red[tid] = m;
    __syncthreads();
    for (int s = 128; s > 0; s >>= 1) {
        if (tid < s) red[tid] = fmaxf(red[tid], red[tid + s]);
        __syncthreads();
    }
    m = red[0];
    __syncthreads();
    float ds = 0.0f;
    for (int j = tid; j < deg; j += 256) ds += __expf(g_elog[off + j] - m);
    red[tid] = ds;
    __syncthreads();
    for (int s = 128; s > 0; s >>= 1) {
        if (tid < s) red[tid] += red[tid + s];
        __syncthreads();
    }
    float eself_x = __expf(eself - m);
    float inv = 1.0f / (red[0] + eself_x);
    __syncthreads();

    int nr = F >> 8;  // F in {256,512,1024}
    float acc[4];
    const float* xln = &g_xl[(size_t)n * F];
    float aself = eself_x * inv;
    for (int r = 0; r < nr; r++) acc[r] = aself * xln[tid + (r << 8)];

    for (int c0 = 0; c0 < deg; c0 += 128) {
        int cnt = min(128, deg - c0);
        if (tid < cnt) {
            s_alpha[tid] = __expf(g_elog[off + c0 + tid] - m) * inv;
            s_src[tid] = g_ssrc[off + c0 + tid];
        }
        __syncthreads();
        for (int j = 0; j < cnt; j++) {
            const float* xs = &g_xl[(size_t)s_src[j] * F];
            float a = s_alpha[j];
            for (int r = 0; r < nr; r++) acc[r] += a * xs[tid + (r << 8)];
        }
        __syncthreads();
    }
    for (int r = 0; r < nr; r++) {
        int f = tid + (r << 8);
        out[(size_t)n * F + f] = fmaxf(acc[r] + bc[f], 0.0f);
    }
}

// ---------------- pooling ----------------
__global__ void pool_acc(const float* __restrict__ h, const int* __restrict__ batch) {
    int i = blockIdx.x * blockDim.x + threadIdx.x;
    if (i >= N_NODES * 256) return;
    int n = i >> 8, f = i & 255;
    atomicAdd(&g_pool[batch[n] * 256 + f], h[i]);
}
__global__ void cnt_acc(const int* __restrict__ batch) {
    int i = blockIdx.x * blockDim.x + threadIdx.x;
    if (i < N_NODES) atomicAdd(&g_gcnt[batch[i]], 1);
}

// ---------------- MLP head (single block) ----------------
__global__ __launch_bounds__(256) void mlp_head(
    const float* __restrict__ fc1w, const float* __restrict__ fc1b,
    const float* __restrict__ bng, const float* __restrict__ bnb,
    const float* __restrict__ fc2w, const float* __restrict__ fc2b,
    float* __restrict__ out) {
    __shared__ float z[NGRAPH * 64];
    __shared__ float mu[64], iv[64];
    int tid = threadIdx.x;
    for (int i = tid; i < NGRAPH * 64; i += 256) {
        int g = i >> 6, o = i & 63;
        float cnt = fmaxf((float)g_gcnt[g], 1.0f);
        float s = 0.0f;
        for (int k = 0; k < 256; k++) s += g_pool[g * 256 + k] * fc1w[k * 64 + o];
        z[i] = s / cnt + fc1b[o];
    }
    __syncthreads();
    if (tid < 64) {
        float s = 0.0f, s2 = 0.0f;
        for (int g = 0; g < NGRAPH; g++) {
            float v = z[g * 64 + tid];
            s += v; s2 += v * v;
        }
        float mean = s / (float)NGRAPH;
        float var = s2 / (float)NGRAPH - mean * mean;
        mu[tid] = mean;
        iv[tid] = rsqrtf(var + 1e-5f);
    }
    __syncthreads();
    for (int i = tid; i < NGRAPH * 64; i += 256) {
        int o = i & 63;
        float v = (z[i] - mu[o]) * iv[o] * bng[o] + bnb[o];
        z[i] = fmaxf(v, 0.0f);
    }
    __syncthreads();
    if (tid < NGRAPH) {
        float s = 0.0f;
        for (int o = 0; o < 64; o++) s += z[tid * 64 + o] * fc2w[o];
        out[tid] = s + fc2b[0];
    }
}

// ---------------- host-side layer driver ----------------
static void run_layer(const float* hin, int Fin, int Fout, float* hout,
                      const float* Wl, const float* bl,
                      const float* Wr, const float* br,
                      const float* We, const float* att, const float* bc,
                      const float* edge_attr,
                      float* d_xl, float* d_xr, float* d_eaWe, float* d_loopWe,
                      float* d_loop_attr) {
    dim3 t(256);
    // xl = hin@Wl + bl ; xr = hin@Wr + br
    {
        dim3 g(Fout / 128, N_NODES / 128);
        gemm_fp16x2_bias<<<g, t>>>(hin, Wl, bl, d_xl, N_NODES, Fout, Fin);
        gemm_fp16x2_bias<<<g, t>>>(hin, Wr, br, d_xr, N_NODES, Fout, Fin);
    }
    // eaWe = edge_attr @ We ; loopWe = loop_attr @ We
    {
        dim3 g(Fout / 128, N_EDGES / 128);
        gemm_fp16x2_bias<<<g, t>>>(edge_attr, We, nullptr, d_eaWe, N_EDGES, Fout, ED);
        dim3 g2(Fout / 128, N_NODES / 128);
        gemm_fp16x2_bias<<<g2, t>>>(d_loop_attr, We, nullptr, d_loopWe, N_NODES, Fout, ED);
    }
    edge_logit<<<(N_EDGES * 32 + 255) / 256, 256>>>(att, Fout);
    self_logit<<<(N_NODES * 32 + 255) / 256, 256>>>(att, Fout);
    aggregate<<<N_NODES, 256>>>(bc, hout, Fout);
}

extern "C" void kernel_launch(void* const* d_in, const int* in_sizes, int n_in,
                              void* d_out, int out_size) {
    const float* x         = (const float*)d_in[0];
    const int*   ei        = (const int*)d_in[1];
    const float* edge_attr = (const float*)d_in[2];
    const int*   batch     = (const int*)d_in[3];

    const float* Wl[3], *bl[3], *Wr[3], *br[3], *We[3], *att[3], *bc[3];
    for (int l = 0; l < 3; l++) {
        int b = 4 + l * 7;
        Wl[l]  = (const float*)d_in[b + 0];
        bl[l]  = (const float*)d_in[b + 1];
        Wr[l]  = (const float*)d_in[b + 2];
        br[l]  = (const float*)d_in[b + 3];
        We[l]  = (const float*)d_in[b + 4];
        att[l] = (const float*)d_in[b + 5];
        bc[l]  = (const float*)d_in[b + 6];
    }
    const float* fc1w = (const float*)d_in[25];
    const float* fc1b = (const float*)d_in[26];
    const float* bng  = (const float*)d_in[27];
    const float* bnb  = (const float*)d_in[28];
    const float* fc2w = (const float*)d_in[29];
    const float* fc2b = (const float*)d_in[30];
    float* out = (float*)d_out;

    const int* src = ei;
    const int* dst = ei + N_EDGES;

    float *d_hA, *d_hB, *d_xl, *d_xr, *d_eaWe, *d_loopWe, *d_loop_attr, *d_pool;
    int *d_deg, *d_cur, *d_gcnt;
    cudaGetSymbolAddress((void**)&d_hA, g_hA);
    cudaGetSymbolAddress((void**)&d_hB, g_hB);
    cudaGetSymbolAddress((void**)&d_xl, g_xl);
    cudaGetSymbolAddress((void**)&d_xr, g_xr);
    cudaGetSymbolAddress((void**)&d_eaWe, g_eaWe);
    cudaGetSymbolAddress((void**)&d_loopWe, g_loopWe);
    cudaGetSymbolAddress((void**)&d_loop_attr, g_loop_attr);
    cudaGetSymbolAddress((void**)&d_pool, g_pool);
    cudaGetSymbolAddress((void**)&d_deg, g_deg);
    cudaGetSymbolAddress((void**)&d_cur, g_cur);
    cudaGetSymbolAddress((void**)&d_gcnt, g_gcnt);

    // ---- graph preprocessing ----
    zero_i<<<(N_NODES + 255) / 256, 256>>>(d_deg, N_NODES);
    zero_i<<<(N_NODES + 255) / 256, 256>>>(d_cur, N_NODES);
    zero_i<<<(NGRAPH + 255) / 256, 256>>>(d_gcnt, NGRAPH);
    zero_f<<<(N_NODES * ED + 255) / 256, 256>>>(d_loop_attr, N_NODES * ED);
    zero_f<<<(NGRAPH * 256 + 255) / 256, 256>>>(d_pool, NGRAPH * 256);

    count_deg<<<(N_EDGES + 255) / 256, 256>>>(dst);
    acc_loop_attr<<<(N_EDGES * ED + 255) / 256, 256>>>(dst, edge_attr);
    scan_deg<<<1, 1024>>>();
    scatter_edges<<<(N_EDGES + 255) / 256, 256>>>(src, dst);
    div_loop_attr<<<(N_NODES * ED + 255) / 256, 256>>>();

    // ---- 3 GATv2 layers ----
    run_layer(x,    256,  512, d_hA, Wl[0], bl[0], Wr[0], br[0], We[0], att[0], bc[0],
              edge_attr, d_xl, d_xr, d_eaWe, d_loopWe, d_loop_attr);
    run_layer(d_hA, 512, 1024, d_hB, Wl[1], bl[1], Wr[1], br[1], We[1], att[1], bc[1],
              edge_attr, d_xl, d_xr, d_eaWe, d_loopWe, d_loop_attr);
    run_layer(d_hB, 1024, 256, d_hA, Wl[2], bl[2], Wr[2], br[2], We[2], att[2], bc[2],
              edge_attr, d_xl, d_xr, d_eaWe, d_loopWe, d_loop_attr);

    // ---- pool + MLP head ----
    cnt_acc<<<(N_NODES + 255) / 256, 256>>>(batch);
    pool_acc<<<(N_NODES * 256 + 255) / 256, 256>>>(d_hA, batch);
    mlp_head<<<1, 256>>>(fc1w, fc1b, bng, bnb, fc2w, fc2b, out);
}

// round 4
// speedup vs baseline: 2.4547x; 1.3337x over previous
#include <cuda_runtime.h>
#include <cuda_fp16.h>
#include <mma.h>
#include <cstdint>

using namespace nvcuda;

#define N_NODES 16384
#define N_EDGES 131072
#define ED      32
#define NGRAPH  128
#define MAXF    1024
#define NEG_SLOPE 0.2f

// ---------------- scratch (static device memory; no allocs) ----------------
__device__ float g_hA[(size_t)N_NODES * MAXF];
__device__ float g_hB[(size_t)N_NODES * MAXF];
__device__ float g_xl[(size_t)N_NODES * MAXF];
__device__ float g_xr[(size_t)N_NODES * MAXF];
__device__ float g_loop_attr[N_NODES * ED];
__device__ int   g_deg[N_NODES];
__device__ int   g_off[N_NODES + 1];
__device__ int   g_cur[N_NODES];
__device__ int   g_ssrc[N_EDGES];
__device__ int   g_sdst[N_EDGES];
__device__ int   g_seid[N_EDGES];
__device__ float g_elog[N_EDGES];
__device__ float g_eself[N_NODES];
__device__ float g_pool[NGRAPH * 256];
__device__ int   g_gcnt[NGRAPH];
__device__ float g_z[NGRAPH * 64];

// ---------------- utility kernels ----------------
__global__ void zero_f(float* p, int n) {
    int i = blockIdx.x * blockDim.x + threadIdx.x;
    if (i < n) p[i] = 0.0f;
}
__global__ void zero_i(int* p, int n) {
    int i = blockIdx.x * blockDim.x + threadIdx.x;
    if (i < n) p[i] = 0;
}

__global__ void count_deg(const int* __restrict__ dst) {
    int i = blockIdx.x * blockDim.x + threadIdx.x;
    if (i < N_EDGES) atomicAdd(&g_deg[dst[i]], 1);
}

// exclusive scan of g_deg[16384] -> g_off, single block of 1024 threads
__global__ void scan_deg() {
    __shared__ int part[1024];
    int tid = threadIdx.x;
    int base = tid * 16;
    int loc[16];
    int s = 0;
#pragma unroll
    for (int k = 0; k < 16; k++) { loc[k] = s; s += g_deg[base + k]; }
    part[tid] = s;
    __syncthreads();
    for (int d = 1; d < 1024; d <<= 1) {
        int v = (tid >= d) ? part[tid - d] : 0;
        __syncthreads();
        part[tid] += v;
        __syncthreads();
    }
    int pre = (tid == 0) ? 0 : part[tid - 1];
#pragma unroll
    for (int k = 0; k < 16; k++) g_off[base + k] = pre + loc[k];
    if (tid == 1023) g_off[N_NODES] = part[1023];
}

__global__ void scatter_edges(const int* __restrict__ src, const int* __restrict__ dst) {
    int i = blockIdx.x * blockDim.x + threadIdx.x;
    if (i >= N_EDGES) return;
    int d = dst[i];
    int p = g_off[d] + atomicAdd(&g_cur[d], 1);
    g_ssrc[p] = src[i];
    g_sdst[p] = d;
    g_seid[p] = i;
}

// loop_attr[n] = mean of edge_attr over incoming edges (CSR, no atomics)
__global__ void loop_attr_csr(const float* __restrict__ ea) {
    int w = (blockIdx.x * blockDim.x + threadIdx.x) >> 5;
    int lane = threadIdx.x & 31;
    if (w >= N_NODES) return;
    int off = g_off[w], deg = g_off[w + 1] - off;
    float a = 0.0f;
    for (int j = 0; j < deg; j++)
        a += ea[(size_t)g_seid[off + j] * ED + lane];
    g_loop_attr[w * ED + lane] = a / fmaxf((float)deg, 1.0f);
}

// ------- fp16x2-split tensor-core GEMM: C[M,N] = A[M,K] @ B[K,N] (+bias) -------
__global__ __launch_bounds__(256) void gemm_fp16x2_bias(
    const float* __restrict__ A, const float* __restrict__ B,
    const float* __restrict__ bias, float* __restrict__ C,
    int M, int N, int K) {
    constexpr int BM = 128, BN = 128, BK = 32;
    constexpr int LDA = BK + 8;   // 40 halves
    constexpr int LDB = BN + 8;   // 136 halves
    __shared__ __align__(16) __half As[2][BM * LDA];
    __shared__ __align__(16) __half Bs[2][BK * LDB];

    int tid = threadIdx.x;
    int warp = tid >> 5, lane = tid & 31;
    int wr = warp >> 2;
    int wc = warp & 3;
    int row0 = blockIdx.y * BM, col0 = blockIdx.x * BN;

    wmma::fragment<wmma::accumulator, 16, 16, 16, float> cf[4][2];
#pragma unroll
    for (int r = 0; r < 4; r++)
#pragma unroll
        for (int c = 0; c < 2; c++) wmma::fill_fragment(cf[r][c], 0.0f);

    for (int k0 = 0; k0 < K; k0 += BK) {
#pragma unroll
        for (int q = 0; q < 4; q++) {
            int lin = tid + q * 256;
            int r = lin >> 3, c4 = lin & 7;
            float4 v = *reinterpret_cast<const float4*>(&A[(size_t)(row0 + r) * K + k0 + c4 * 4]);
            float vv[4] = {v.x, v.y, v.z, v.w};
            int base = r * LDA + c4 * 4;
#pragma unroll
            for (int i = 0; i < 4; i++) {
                __half h = __float2half_rn(vv[i]);
                As[0][base + i] = h;
                As[1][base + i] = __float2half_rn(vv[i] - __half2float(h));
            }
        }
#pragma unroll
        for (int q = 0; q < 4; q++) {
            int lin = tid + q * 256;
            int r = lin >> 5, c4 = lin & 31;
            float4 v = *reinterpret_cast<const float4*>(&B[(size_t)(k0 + r) * N + col0 + c4 * 4]);
            float vv[4] = {v.x, v.y, v.z, v.w};
            int base = r * LDB + c4 * 4;
#pragma unroll
            for (int i = 0; i < 4; i++) {
                __half h = __float2half_rn(vv[i]);
                Bs[0][base + i] = h;
                Bs[1][base + i] = __float2half_rn(vv[i] - __half2float(h));
            }
        }
        __syncthreads();
#pragma unroll
        for (int ks = 0; ks < BK / 16; ks++) {
            wmma::fragment<wmma::matrix_a, 16, 16, 16, __half, wmma::row_major> ah[4], al[4];
            wmma::fragment<wmma::matrix_b, 16, 16, 16, __half, wmma::row_major> bh[2], bl[2];
#pragma unroll
            for (int r = 0; r < 4; r++) {
                int aoff = (wr * 64 + r * 16) * LDA + ks * 16;
                wmma::load_matrix_sync(ah[r], &As[0][aoff], LDA);
                wmma::load_matrix_sync(al[r], &As[1][aoff], LDA);
            }
#pragma unroll
            for (int c = 0; c < 2; c++) {
                int boff = (ks * 16) * LDB + wc * 32 + c * 16;
                wmma::load_matrix_sync(bh[c], &Bs[0][boff], LDB);
                wmma::load_matrix_sync(bl[c], &Bs[1][boff], LDB);
            }
#pragma unroll
            for (int r = 0; r < 4; r++)
#pragma unroll
                for (int c = 0; c < 2; c++) {
                    wmma::mma_sync(cf[r][c], ah[r], bl[c], cf[r][c]);
                    wmma::mma_sync(cf[r][c], al[r], bh[c], cf[r][c]);
                    wmma::mma_sync(cf[r][c], ah[r], bh[c], cf[r][c]);
                }
        }
        __syncthreads();
    }

    float* Ep = reinterpret_cast<float*>(&As[0][0]) + warp * 16 * 20;
    int erow = lane >> 1;
    int ecol = (lane & 1) * 8;
#pragma unroll
    for (int r = 0; r < 4; r++) {
#pragma unroll
        for (int c = 0; c < 2; c++) {
            wmma::store_matrix_sync(Ep, cf[r][c], 20, wmma::mem_row_major);
            __syncwarp();
            int rr = row0 + wr * 64 + r * 16 + erow;
            int cc = col0 + wc * 32 + c * 16 + ecol;
            float4 v0 = *reinterpret_cast<float4*>(&Ep[erow * 20 + ecol]);
            float4 v1 = *reinterpret_cast<float4*>(&Ep[erow * 20 + ecol + 4]);
            if (bias) {
                float4 b0 = *reinterpret_cast<const float4*>(&bias[cc]);
                float4 b1 = *reinterpret_cast<const float4*>(&bias[cc + 4]);
                v0.x += b0.x; v0.y += b0.y; v0.z += b0.z; v0.w += b0.w;
                v1.x += b1.x; v1.y += b1.y; v1.z += b1.z; v1.w += b1.w;
            }
            *reinterpret_cast<float4*>(&C[(size_t)rr * N + cc])     = v0;
            *reinterpret_cast<float4*>(&C[(size_t)rr * N + cc + 4]) = v1;
            __syncwarp();
        }
    }
}

// ------- fused attention logits: on-the-fly ea@We (fp16x2 wmma) + leakyrelu dot -------
// tile = 128 items (edges when mode=0, nodes/self-loops when mode=1).
// smem: ea split hi/lo [128x40]h, We chunk split [32x136]h, z [128x132]f, idx [2x128]i
#define FL_LDE 40
#define FL_LDW 136
#define FL_LDZ 132
#define FL_SMEM (2*128*FL_LDE*2 + 2*32*FL_LDW*2 + 128*FL_LDZ*4 + 2*128*4)

__global__ __launch_bounds__(256) void fused_logit(
    const float* __restrict__ ea_src, const float* __restrict__ We,
    const float* __restrict__ att,
    const float* __restrict__ xl, const float* __restrict__ xr,
    float* __restrict__ out_log, int F, int mode) {
    extern __shared__ char sm_raw[];
    __half* ea_h = reinterpret_cast<__half*>(sm_raw);
    __half* ea_l = ea_h + 128 * FL_LDE;
    __half* w_h  = ea_l + 128 * FL_LDE;
    __half* w_l  = w_h + 32 * FL_LDW;
    float*  sz   = reinterpret_cast<float*>(w_l + 32 * FL_LDW);
    int* s_src = reinterpret_cast<int*>(sz + 128 * FL_LDZ);
    int* s_dst = s_src + 128;

    int tid = threadIdx.x, warp = tid >> 5, lane = tid & 31;
    int wr = warp >> 2, wc = warp & 3;
    int tile0 = blockIdx.x * 128;

    if (tid < 128) {
        if (mode == 0) { s_src[tid] = g_ssrc[tile0 + tid]; s_dst[tid] = g_sdst[tile0 + tid]; }
        else           { s_src[tid] = tile0 + tid;         s_dst[tid] = tile0 + tid; }
    }
    // gather + split ea tile (128 rows x 32)
#pragma unroll
    for (int q = 0; q < 4; q++) {
        int lin = tid + q * 256;
        int r = lin >> 3, c4 = lin & 7;
        int row = (mode == 0) ? g_seid[tile0 + r] : (tile0 + r);
        float4 v = *reinterpret_cast<const float4*>(&ea_src[(size_t)row * ED + c4 * 4]);
        float vv[4] = {v.x, v.y, v.z, v.w};
        int base = r * FL_LDE + c4 * 4;
#pragma unroll
        for (int i = 0; i < 4; i++) {
            __half h = __float2half_rn(vv[i]);
            ea_h[base + i] = h;
            ea_l[base + i] = __float2half_rn(vv[i] - __half2float(h));
        }
    }
    __syncthreads();

    float acc[16];
#pragma unroll
    for (int e = 0; e < 16; e++) acc[e] = 0.0f;
    int we0 = warp * 16;

    for (int f0 = 0; f0 < F; f0 += 128) {
        // load + split We chunk (32 x 128)
#pragma unroll
        for (int q = 0; q < 4; q++) {
            int lin = tid + q * 256;
            int r = lin >> 5, c4 = lin & 31;
            float4 v = *reinterpret_cast<const float4*>(&We[(size_t)r * F + f0 + c4 * 4]);
            float vv[4] = {v.x, v.y, v.z, v.w};
            int base = r * FL_LDW + c4 * 4;
#pragma unroll
            for (int i = 0; i < 4; i++) {
                __half h = __float2half_rn(vv[i]);
                w_h[base + i] = h;
                w_l[base + i] = __float2half_rn(vv[i] - __half2float(h));
            }
        }
        __syncthreads();

        // z[128x128] = ea(128x32) @ We_chunk(32x128)
        wmma::fragment<wmma::accumulator, 16, 16, 16, float> cf[4][2];
#pragma unroll
        for (int r = 0; r < 4; r++)
#pragma unroll
            for (int c = 0; c < 2; c++) wmma::fill_fragment(cf[r][c], 0.0f);
#pragma unroll
        for (int ks = 0; ks < 2; ks++) {
            wmma::fragment<wmma::matrix_a, 16, 16, 16, __half, wmma::row_major> ah[4], al[4];
            wmma::fragment<wmma::matrix_b, 16, 16, 16, __half, wmma::row_major> bh[2], bl[2];
#pragma unroll
            for (int r = 0; r < 4; r++) {
                int aoff = (wr * 64 + r * 16) * FL_LDE + ks * 16;
                wmma::load_matrix_sync(ah[r], &ea_h[aoff], FL_LDE);
                wmma::load_matrix_sync(al[r], &ea_l[aoff], FL_LDE);
            }
#pragma unroll
            for (int c = 0; c < 2; c++) {
                int boff = (ks * 16) * FL_LDW + wc * 32 + c * 16;
                wmma::load_matrix_sync(bh[c], &w_h[boff], FL_LDW);
                wmma::load_matrix_sync(bl[c], &w_l[boff], FL_LDW);
            }
#pragma unroll
            for (int r = 0; r < 4; r++)
#pragma unroll
                for (int c = 0; c < 2; c++) {
                    wmma::mma_sync(cf[r][c], ah[r], bl[c], cf[r][c]);
                    wmma::mma_sync(cf[r][c], al[r], bh[c], cf[r][c]);
                    wmma::mma_sync(cf[r][c], ah[r], bh[c], cf[r][c]);
                }
        }
#pragma unroll
        for (int r = 0; r < 4; r++)
#pragma unroll
            for (int c = 0; c < 2; c++)
                wmma::store_matrix_sync(&sz[(wr * 64 + r * 16) * FL_LDZ + wc * 32 + c * 16],
                                        cf[r][c], FL_LDZ, wmma::mem_row_major);
        __syncthreads();

        // partial dot with leakyrelu
        float av[4];
#pragma unroll
        for (int t = 0; t < 4; t++) av[t] = att[f0 + lane + t * 32];
#pragma unroll
        for (int e = 0; e < 16; e++) {
            int idx = we0 + e;
            const float* pl = xl + (size_t)s_src[idx] * F + f0;
            const float* pr = xr + (size_t)s_dst[idx] * F + f0;
            const float* pz = &sz[idx * FL_LDZ];
            float a = 0.0f;
#pragma unroll
            for (int t = 0; t < 4; t++) {
                int f = lane + t * 32;
                float v = pl[f] + pr[f] + pz[f];
                v = (v > 0.0f) ? v : NEG_SLOPE * v;
                a += v * av[t];
            }
            acc[e] += a;
        }
        __syncthreads();
    }
#pragma unroll
    for (int e = 0; e < 16; e++) {
        float a = acc[e];
#pragma unroll
        for (int o = 16; o; o >>= 1) a += __shfl_xor_sync(0xffffffffu, a, o);
        if (lane == 0) out_log[tile0 + we0 + e] = a;
    }
}

// ---------------- per-destination softmax + aggregate (+bias+relu) ----------------
__global__ __launch_bounds__(256) void aggregate(const float* __restrict__ bc,
                                                 float* __restrict__ out, int F) {
    int n = blockIdx.x;
    int tid = threadIdx.x;
    int off = g_off[n];
    int deg = g_off[n + 1] - off;
    __shared__ float red[256];
    __shared__ float s_alpha[128];
    __shared__ int s_src[128];

    float eself = g_eself[n];
    float m = eself;
    for (int j = tid; j < deg; j += 256) m = fmaxf(m, g_elog[off + j]);
    red[tid] = m;
    __syncthreads();
    for (int s = 128; s > 0; s >>= 1) {
        if (tid < s) red[tid] = fmaxf(red[tid], red[tid + s]);
        __syncthreads();
    }
    m = red[0];
    __syncthreads();
    float ds = 0.0f;
    for (int j = tid; j < deg; j += 256) ds += __expf(g_elog[off + j] - m);
    red[tid] = ds;
    __syncthreads();
    for (int s = 128; s > 0; s >>= 1) {
        if (tid < s) red[tid] += red[tid + s];
        __syncthreads();
    }
    float eself_x = __expf(eself - m);
    float inv = 1.0f / (red[0] + eself_x);
    __syncthreads();

    int nr = F >> 8;
    float acc[4];
    const float* xln = &g_xl[(size_t)n * F];
    float aself = eself_x * inv;
    for (int r = 0; r < nr; r++) acc[r] = aself * xln[tid + (r << 8)];

    for (int c0 = 0; c0 < deg; c0 += 128) {
        int cnt = min(128, deg - c0);
        if (tid < cnt) {
            s_alpha[tid] = __expf(g_elog[off + c0 + tid] - m) * inv;
            s_src[tid] = g_ssrc[off + c0 + tid];
        }
        __syncthreads();
        for (int j = 0; j < cnt; j++) {
            const float* xs = &g_xl[(size_t)s_src[j] * F];
            float a = s_alpha[j];
            for (int r = 0; r < nr; r++) acc[r] += a * xs[tid + (r << 8)];
        }
        __syncthreads();
    }
    for (int r = 0; r < nr; r++) {
        int f = tid + (r << 8);
        out[(size_t)n * F + f] = fmaxf(acc[r] + bc[f], 0.0f);
    }
}

// ---------------- pooling ----------------
__global__ void pool_acc(const float* __restrict__ h, const int* __restrict__ batch) {
    int i = blockIdx.x * blockDim.x + threadIdx.x;
    if (i >= N_NODES * 256) return;
    int n = i >> 8, f = i & 255;
    atomicAdd(&g_pool[batch[n] * 256 + f], h[i]);
}
__global__ void cnt_acc(const int* __restrict__ batch) {
    int i = blockIdx.x * blockDim.x + threadIdx.x;
    if (i < N_NODES) atomicAdd(&g_gcnt[batch[i]], 1);
}

// ---------------- MLP head ----------------
__global__ void fc1_kernel(const float* __restrict__ fc1w, const float* __restrict__ fc1b) {
    int i = blockIdx.x * blockDim.x + threadIdx.x;
    if (i >= NGRAPH * 64) return;
    int g = i >> 6, o = i & 63;
    float cnt = fmaxf((float)g_gcnt[g], 1.0f);
    float s = 0.0f;
    for (int k = 0; k < 256; k++) s += g_pool[g * 256 + k] * fc1w[k * 64 + o];
    g_z[i] = s / cnt + fc1b[o];
}

__global__ __launch_bounds__(256) void head_kernel(
    const float* __restrict__ bng, const float* __restrict__ bnb,
    const float* __restrict__ fc2w, const float* __restrict__ fc2b,
    float* __restrict__ out) {
    __shared__ float z[NGRAPH * 64];
    __shared__ float mu[64], iv[64];
    int tid = threadIdx.x;
    for (int i = tid; i < NGRAPH * 64; i += 256) z[i] = g_z[i];
    __syncthreads();
    if (tid < 64) {
        float s = 0.0f, s2 = 0.0f;
        for (int g = 0; g < NGRAPH; g++) {
            float v = z[g * 64 + tid];
            s += v; s2 += v * v;
        }
        float mean = s / (float)NGRAPH;
        float var = s2 / (float)NGRAPH - mean * mean;
        mu[tid] = mean;
        iv[tid] = rsqrtf(var + 1e-5f);
    }
    __syncthreads();
    for (int i = tid; i < NGRAPH * 64; i += 256) {
        int o = i & 63;
        float v = (z[i] - mu[o]) * iv[o] * bng[o] + bnb[o];
        z[i] = fmaxf(v, 0.0f);
    }
    __syncthreads();
    if (tid < NGRAPH) {
        float s = 0.0f;
        for (int o = 0; o < 64; o++) s += z[tid * 64 + o] * fc2w[o];
        out[tid] = s + fc2b[0];
    }
}

// ---------------- host-side layer driver ----------------
static void run_layer(const float* hin, int Fin, int Fout, float* hout,
                      const float* Wl, const float* bl,
                      const float* Wr, const float* br,
                      const float* We, const float* att, const float* bc,
                      const float* edge_attr,
                      float* d_xl, float* d_xr, float* d_loop_attr,
                      float* d_elog, float* d_eself) {
    dim3 t(256);
    dim3 g(Fout / 128, N_NODES / 128);
    gemm_fp16x2_bias<<<g, t>>>(hin, Wl, bl, d_xl, N_NODES, Fout, Fin);
    gemm_fp16x2_bias<<<g, t>>>(hin, Wr, br, d_xr, N_NODES, Fout, Fin);
    fused_logit<<<N_EDGES / 128, 256, FL_SMEM>>>(edge_attr, We, att, d_xl, d_xr,
                                                 d_elog, Fout, 0);
    fused_logit<<<N_NODES / 128, 256, FL_SMEM>>>(d_loop_attr, We, att, d_xl, d_xr,
                                                 d_eself, Fout, 1);
    aggregate<<<N_NODES, 256>>>(bc, hout, Fout);
}

extern "C" void kernel_launch(void* const* d_in, const int* in_sizes, int n_in,
                              void* d_out, int out_size) {
    const float* x         = (const float*)d_in[0];
    const int*   ei        = (const int*)d_in[1];
    const float* edge_attr = (const float*)d_in[2];
    const int*   batch     = (const int*)d_in[3];

    const float* Wl[3], *bl[3], *Wr[3], *br[3], *We[3], *att[3], *bc[3];
    for (int l = 0; l < 3; l++) {
        int b = 4 + l * 7;
        Wl[l]  = (const float*)d_in[b + 0];
        bl[l]  = (const float*)d_in[b + 1];
        Wr[l]  = (const float*)d_in[b + 2];
        br[l]  = (const float*)d_in[b + 3];
        We[l]  = (const float*)d_in[b + 4];
        att[l] = (const float*)d_in[b + 5];
        bc[l]  = (const float*)d_in[b + 6];
    }
    const float* fc1w = (const float*)d_in[25];
    const float* fc1b = (const float*)d_in[26];
    const float* bng  = (const float*)d_in[27];
    const float* bnb  = (const float*)d_in[28];
    const float* fc2w = (const float*)d_in[29];
    const float* fc2b = (const float*)d_in[30];
    float* out = (float*)d_out;

    const int* src = ei;
    const int* dst = ei + N_EDGES;

    static bool attr_set = false;
    if (!attr_set) {
        cudaFuncSetAttribute(fused_logit, cudaFuncAttributeMaxDynamicSharedMemorySize, FL_SMEM);
        attr_set = true;
    }

    float *d_hA, *d_hB, *d_xl, *d_xr, *d_loop_attr, *d_pool, *d_elog, *d_eself;
    int *d_deg, *d_cur, *d_gcnt;
    cudaGetSymbolAddress((void**)&d_hA, g_hA);
    cudaGetSymbolAddress((void**)&d_hB, g_hB);
    cudaGetSymbolAddress((void**)&d_xl, g_xl);
    cudaGetSymbolAddress((void**)&d_xr, g_xr);
    cudaGetSymbolAddress((void**)&d_loop_attr, g_loop_attr);
    cudaGetSymbolAddress((void**)&d_pool, g_pool);
    cudaGetSymbolAddress((void**)&d_elog, g_elog);
    cudaGetSymbolAddress((void**)&d_eself, g_eself);
    cudaGetSymbolAddress((void**)&d_deg, g_deg);
    cudaGetSymbolAddress((void**)&d_cur, g_cur);
    cudaGetSymbolAddress((void**)&d_gcnt, g_gcnt);

    // launches 0-4 (so ncu -s 5 captures the first GEMM next)
    zero_i<<<(N_NODES + 255) / 256, 256>>>(d_deg, N_NODES);
    zero_i<<<(N_NODES + 255) / 256, 256>>>(d_cur, N_NODES);
    zero_i<<<(NGRAPH + 255) / 256, 256>>>(d_gcnt, NGRAPH);
    zero_f<<<(NGRAPH * 256 + 255) / 256, 256>>>(d_pool, NGRAPH * 256);
    count_deg<<<(N_EDGES + 255) / 256, 256>>>(dst);

    // launch 5: layer-1 xl GEMM (profiled), 6: xr GEMM — independent of preprocessing
    {
        dim3 g(512 / 128, N_NODES / 128);
        gemm_fp16x2_bias<<<g, dim3(256)>>>(x, Wl[0], bl[0], d_xl, N_NODES, 512, 256);
        gemm_fp16x2_bias<<<g, dim3(256)>>>(x, Wr[0], br[0], d_xr, N_NODES, 512, 256);
    }

    // rest of preprocessing
    scan_deg<<<1, 1024>>>();
    scatter_edges<<<(N_EDGES + 255) / 256, 256>>>(src, dst);
    loop_attr_csr<<<(N_NODES * 32 + 255) / 256, 256>>>(edge_attr);
    cnt_acc<<<(N_NODES + 255) / 256, 256>>>(batch);

    // layer 1 (GEMMs already issued)
    fused_logit<<<N_EDGES / 128, 256, FL_SMEM>>>(edge_attr, We[0], att[0], d_xl, d_xr,
                                                 d_elog, 512, 0);
    fused_logit<<<N_NODES / 128, 256, FL_SMEM>>>(d_loop_attr, We[0], att[0], d_xl, d_xr,
                                                 d_eself, 512, 1);
    aggregate<<<N_NODES, 256>>>(bc[0], d_hA, 512);

    // layers 2, 3
    run_layer(d_hA, 512, 1024, d_hB, Wl[1], bl[1], Wr[1], br[1], We[1], att[1], bc[1],
              edge_attr, d_xl, d_xr, d_loop_attr, d_elog, d_eself);
    run_layer(d_hB, 1024, 256, d_hA, Wl[2], bl[2], Wr[2], br[2], We[2], att[2], bc[2],
              edge_attr, d_xl, d_xr, d_loop_attr, d_elog, d_eself);

    // pool + MLP head
    pool_acc<<<(N_NODES * 256 + 255) / 256, 256>>>(d_hA, batch);
    fc1_kernel<<<(NGRAPH * 64 + 255) / 256, 256>>>(fc1w, fc1b);
    head_kernel<<<1, 256>>>(bng, bnb, fc2w, fc2b, out);
}

// round 5
// speedup vs baseline: 2.7250x; 1.1101x over previous
#include <cuda_runtime.h>
#include <cuda_fp16.h>
#include <mma.h>
#include <cstdint>

using namespace nvcuda;

#define N_NODES 16384
#define N_EDGES 131072
#define ED      32
#define NGRAPH  128
#define MAXF    1024
#define NEG_SLOPE 0.2f

// ---------------- scratch (static device memory; no allocs) ----------------
__device__ float g_hA[(size_t)N_NODES * MAXF];
__device__ float g_hB[(size_t)N_NODES * MAXF];
__device__ float g_xl[(size_t)N_NODES * MAXF];
__device__ float g_xr[(size_t)N_NODES * MAXF];
__device__ float g_loop_attr[N_NODES * ED];
__device__ int   g_deg[N_NODES];
__device__ int   g_off[N_NODES + 1];
__device__ int   g_cur[N_NODES];
__device__ int   g_ssrc[N_EDGES];
__device__ int   g_sdst[N_EDGES];
__device__ int   g_seid[N_EDGES];
__device__ float g_elog[N_EDGES];
__device__ float g_eself[N_NODES];
__device__ float g_pool[NGRAPH * 256];
__device__ float g_z[NGRAPH * 64];

// ---------------- utility kernels ----------------
__global__ void zero_i(int* p, int n) {
    int i = blockIdx.x * blockDim.x + threadIdx.x;
    if (i < n) p[i] = 0;
}

__global__ void count_deg(const int* __restrict__ dst) {
    int i = blockIdx.x * blockDim.x + threadIdx.x;
    if (i < N_EDGES) atomicAdd(&g_deg[dst[i]], 1);
}

// exclusive scan of g_deg[16384] -> g_off, single block of 1024 threads
__global__ void scan_deg() {
    __shared__ int part[1024];
    int tid = threadIdx.x;
    int base = tid * 16;
    int loc[16];
    int s = 0;
#pragma unroll
    for (int k = 0; k < 16; k++) { loc[k] = s; s += g_deg[base + k]; }
    part[tid] = s;
    __syncthreads();
    for (int d = 1; d < 1024; d <<= 1) {
        int v = (tid >= d) ? part[tid - d] : 0;
        __syncthreads();
        part[tid] += v;
        __syncthreads();
    }
    int pre = (tid == 0) ? 0 : part[tid - 1];
#pragma unroll
    for (int k = 0; k < 16; k++) g_off[base + k] = pre + loc[k];
    if (tid == 1023) g_off[N_NODES] = part[1023];
}

__global__ void scatter_edges(const int* __restrict__ src, const int* __restrict__ dst) {
    int i = blockIdx.x * blockDim.x + threadIdx.x;
    if (i >= N_EDGES) return;
    int d = dst[i];
    int p = g_off[d] + atomicAdd(&g_cur[d], 1);
    g_ssrc[p] = src[i];
    g_sdst[p] = d;
    g_seid[p] = i;
}

// loop_attr[n] = mean of edge_attr over incoming edges (CSR, no atomics)
__global__ void loop_attr_csr(const float* __restrict__ ea) {
    int w = (blockIdx.x * blockDim.x + threadIdx.x) >> 5;
    int lane = threadIdx.x & 31;
    if (w >= N_NODES) return;
    int off = g_off[w], deg = g_off[w + 1] - off;
    float a = 0.0f;
    for (int j = 0; j < deg; j++)
        a += ea[(size_t)g_seid[off + j] * ED + lane];
    g_loop_attr[w * ED + lane] = a / fmaxf((float)deg, 1.0f);
}

// ------- fp16x2-split tensor-core GEMM, double-buffered -------
// C[M,N] = A[M,K]@B[K,N] (+bias). BM=BN=128, BK=32. 256 thr = 8 warps (2x4).
// dynamic smem: As hi/lo [2][128*40]h, Bs hi/lo [2][32*136]h = 75776 B
#define GM_LDA 40
#define GM_LDB 136
#define GM_SMEM (2*2*128*GM_LDA*2 + 2*2*32*GM_LDB*2)

__global__ __launch_bounds__(256, 1) void gemm_fp16x2_bias(
    const float* __restrict__ A, const float* __restrict__ B,
    const float* __restrict__ bias, float* __restrict__ C,
    int M, int N, int K) {
    constexpr int BM = 128, BN = 128, BK = 32;
    constexpr int LDA = GM_LDA, LDB = GM_LDB;
    extern __shared__ char gsm[];
    __half* As_h = reinterpret_cast<__half*>(gsm);          // [2][128*LDA]
    __half* As_l = As_h + 2 * BM * LDA;
    __half* Bs_h = As_l + 2 * BM * LDA;                      // [2][32*LDB]
    __half* Bs_l = Bs_h + 2 * BK * LDB;

    int tid = threadIdx.x;
    int warp = tid >> 5, lane = tid & 31;
    int wr = warp >> 2;
    int wc = warp & 3;
    int row0 = blockIdx.y * BM, col0 = blockIdx.x * BN;

    wmma::fragment<wmma::accumulator, 16, 16, 16, float> cf[4][2];
#pragma unroll
    for (int r = 0; r < 4; r++)
#pragma unroll
        for (int c = 0; c < 2; c++) wmma::fill_fragment(cf[r][c], 0.0f);

    float a_pref[16], b_pref[16];

    auto load_regs = [&](int k0) {
#pragma unroll
        for (int q = 0; q < 4; q++) {
            int lin = tid + q * 256;
            int r = lin >> 3, c4 = lin & 7;
            float4 va = *reinterpret_cast<const float4*>(&A[(size_t)(row0 + r) * K + k0 + c4 * 4]);
            a_pref[q * 4 + 0] = va.x; a_pref[q * 4 + 1] = va.y;
            a_pref[q * 4 + 2] = va.z; a_pref[q * 4 + 3] = va.w;
            int rb = lin >> 5, cb = lin & 31;
            float4 vb = *reinterpret_cast<const float4*>(&B[(size_t)(k0 + rb) * N + col0 + cb * 4]);
            b_pref[q * 4 + 0] = vb.x; b_pref[q * 4 + 1] = vb.y;
            b_pref[q * 4 + 2] = vb.z; b_pref[q * 4 + 3] = vb.w;
        }
    };
    auto store_smem = [&](int buf) {
        __half* ah = As_h + buf * BM * LDA;
        __half* al = As_l + buf * BM * LDA;
        __half* bh = Bs_h + buf * BK * LDB;
        __half* bl = Bs_l + buf * BK * LDB;
#pragma unroll
        for (int q = 0; q < 4; q++) {
            int lin = tid + q * 256;
            int r = lin >> 3, c4 = lin & 7;
            int basea = r * LDA + c4 * 4;
#pragma unroll
            for (int i = 0; i < 4; i++) {
                float v = a_pref[q * 4 + i];
                __half h = __float2half_rn(v);
                ah[basea + i] = h;
                al[basea + i] = __float2half_rn(v - __half2float(h));
            }
            int rb = lin >> 5, cb = lin & 31;
            int baseb = rb * LDB + cb * 4;
#pragma unroll
            for (int i = 0; i < 4; i++) {
                float v = b_pref[q * 4 + i];
                __half h = __float2half_rn(v);
                bh[baseb + i] = h;
                bl[baseb + i] = __float2half_rn(v - __half2float(h));
            }
        }
    };
    auto compute = [&](int buf) {
        const __half* ahp = As_h + buf * BM * LDA;
        const __half* alp = As_l + buf * BM * LDA;
        const __half* bhp = Bs_h + buf * BK * LDB;
        const __half* blp = Bs_l + buf * BK * LDB;
#pragma unroll
        for (int ks = 0; ks < 2; ks++) {
            wmma::fragment<wmma::matrix_a, 16, 16, 16, __half, wmma::row_major> ah[4], al[4];
            wmma::fragment<wmma::matrix_b, 16, 16, 16, __half, wmma::row_major> bh[2], bl[2];
#pragma unroll
            for (int r = 0; r < 4; r++) {
                int aoff = (wr * 64 + r * 16) * LDA + ks * 16;
                wmma::load_matrix_sync(ah[r], &ahp[aoff], LDA);
                wmma::load_matrix_sync(al[r], &alp[aoff], LDA);
            }
#pragma unroll
            for (int c = 0; c < 2; c++) {
                int boff = (ks * 16) * LDB + wc * 32 + c * 16;
                wmma::load_matrix_sync(bh[c], &bhp[boff], LDB);
                wmma::load_matrix_sync(bl[c], &blp[boff], LDB);
            }
#pragma unroll
            for (int r = 0; r < 4; r++)
#pragma unroll
                for (int c = 0; c < 2; c++) {
                    wmma::mma_sync(cf[r][c], ah[r], bl[c], cf[r][c]);
                    wmma::mma_sync(cf[r][c], al[r], bh[c], cf[r][c]);
                    wmma::mma_sync(cf[r][c], ah[r], bh[c], cf[r][c]);
                }
        }
    };

    int nk = K / BK;
    load_regs(0);
    store_smem(0);
    __syncthreads();
    int buf = 0;
    for (int t = 1; t < nk; t++) {
        load_regs(t * BK);      // global loads overlap with MMA below
        compute(buf);
        store_smem(buf ^ 1);
        __syncthreads();
        buf ^= 1;
    }
    compute(buf);
    __syncthreads();   // protect epilogue smem reuse

    float* Ep = reinterpret_cast<float*>(gsm) + warp * 16 * 20;
    int erow = lane >> 1;
    int ecol = (lane & 1) * 8;
#pragma unroll
    for (int r = 0; r < 4; r++) {
#pragma unroll
        for (int c = 0; c < 2; c++) {
            wmma::store_matrix_sync(Ep, cf[r][c], 20, wmma::mem_row_major);
            __syncwarp();
            int rr = row0 + wr * 64 + r * 16 + erow;
            int cc = col0 + wc * 32 + c * 16 + ecol;
            float4 v0 = *reinterpret_cast<float4*>(&Ep[erow * 20 + ecol]);
            float4 v1 = *reinterpret_cast<float4*>(&Ep[erow * 20 + ecol + 4]);
            if (bias) {
                float4 b0 = *reinterpret_cast<const float4*>(&bias[cc]);
                float4 b1 = *reinterpret_cast<const float4*>(&bias[cc + 4]);
                v0.x += b0.x; v0.y += b0.y; v0.z += b0.z; v0.w += b0.w;
                v1.x += b1.x; v1.y += b1.y; v1.z += b1.z; v1.w += b1.w;
            }
            *reinterpret_cast<float4*>(&C[(size_t)rr * N + cc])     = v0;
            *reinterpret_cast<float4*>(&C[(size_t)rr * N + cc + 4]) = v1;
            __syncwarp();
        }
    }
}

// ------- fused attention logits: on-the-fly ea@We (fp16x2 wmma) + leakyrelu dot -------
#define FL_LDE 40
#define FL_LDW 136
#define FL_LDZ 132
#define FL_SMEM (2*128*FL_LDE*2 + 2*32*FL_LDW*2 + 128*FL_LDZ*4 + 2*128*4)

__global__ __launch_bounds__(256) void fused_logit(
    const float* __restrict__ ea_src, const float* __restrict__ We,
    const float* __restrict__ att,
    const float* __restrict__ xl, const float* __restrict__ xr,
    float* __restrict__ out_log, int F, int mode) {
    extern __shared__ char sm_raw[];
    __half* ea_h = reinterpret_cast<__half*>(sm_raw);
    __half* ea_l = ea_h + 128 * FL_LDE;
    __half* w_h  = ea_l + 128 * FL_LDE;
    __half* w_l  = w_h + 32 * FL_LDW;
    float*  sz   = reinterpret_cast<float*>(w_l + 32 * FL_LDW);
    int* s_src = reinterpret_cast<int*>(sz + 128 * FL_LDZ);
    int* s_dst = s_src + 128;

    int tid = threadIdx.x, warp = tid >> 5, lane = tid & 31;
    int wr = warp >> 2, wc = warp & 3;
    int tile0 = blockIdx.x * 128;

    if (tid < 128) {
        if (mode == 0) { s_src[tid] = g_ssrc[tile0 + tid]; s_dst[tid] = g_sdst[tile0 + tid]; }
        else           { s_src[tid] = tile0 + tid;         s_dst[tid] = tile0 + tid; }
    }
#pragma unroll
    for (int q = 0; q < 4; q++) {
        int lin = tid + q * 256;
        int r = lin >> 3, c4 = lin & 7;
        int row = (mode == 0) ? g_seid[tile0 + r] : (tile0 + r);
        float4 v = *reinterpret_cast<const float4*>(&ea_src[(size_t)row * ED + c4 * 4]);
        float vv[4] = {v.x, v.y, v.z, v.w};
        int base = r * FL_LDE + c4 * 4;
#pragma unroll
        for (int i = 0; i < 4; i++) {
            __half h = __float2half_rn(vv[i]);
            ea_h[base + i] = h;
            ea_l[base + i] = __float2half_rn(vv[i] - __half2float(h));
        }
    }
    __syncthreads();

    float acc[16];
#pragma unroll
    for (int e = 0; e < 16; e++) acc[e] = 0.0f;
    int we0 = warp * 16;

    for (int f0 = 0; f0 < F; f0 += 128) {
#pragma unroll
        for (int q = 0; q < 4; q++) {
            int lin = tid + q * 256;
            int r = lin >> 5, c4 = lin & 31;
            float4 v = *reinterpret_cast<const float4*>(&We[(size_t)r * F + f0 + c4 * 4]);
            float vv[4] = {v.x, v.y, v.z, v.w};
            int base = r * FL_LDW + c4 * 4;
#pragma unroll
            for (int i = 0; i < 4; i++) {
                __half h = __float2half_rn(vv[i]);
                w_h[base + i] = h;
                w_l[base + i] = __float2half_rn(vv[i] - __half2float(h));
            }
        }
        __syncthreads();

        wmma::fragment<wmma::accumulator, 16, 16, 16, float> cf[4][2];
#pragma unroll
        for (int r = 0; r < 4; r++)
#pragma unroll
            for (int c = 0; c < 2; c++) wmma::fill_fragment(cf[r][c], 0.0f);
#pragma unroll
        for (int ks = 0; ks < 2; ks++) {
            wmma::fragment<wmma::matrix_a, 16, 16, 16, __half, wmma::row_major> ah[4], al[4];
            wmma::fragment<wmma::matrix_b, 16, 16, 16, __half, wmma::row_major> bh[2], bl[2];
#pragma unroll
            for (int r = 0; r < 4; r++) {
                int aoff = (wr * 64 + r * 16) * FL_LDE + ks * 16;
                wmma::load_matrix_sync(ah[r], &ea_h[aoff], FL_LDE);
                wmma::load_matrix_sync(al[r], &ea_l[aoff], FL_LDE);
            }
#pragma unroll
            for (int c = 0; c < 2; c++) {
                int boff = (ks * 16) * FL_LDW + wc * 32 + c * 16;
                wmma::load_matrix_sync(bh[c], &w_h[boff], FL_LDW);
                wmma::load_matrix_sync(bl[c], &w_l[boff], FL_LDW);
            }
#pragma unroll
            for (int r = 0; r < 4; r++)
#pragma unroll
                for (int c = 0; c < 2; c++) {
                    wmma::mma_sync(cf[r][c], ah[r], bl[c], cf[r][c]);
                    wmma::mma_sync(cf[r][c], al[r], bh[c], cf[r][c]);
                    wmma::mma_sync(cf[r][c], ah[r], bh[c], cf[r][c]);
                }
        }
#pragma unroll
        for (int r = 0; r < 4; r++)
#pragma unroll
            for (int c = 0; c < 2; c++)
                wmma::store_matrix_sync(&sz[(wr * 64 + r * 16) * FL_LDZ + wc * 32 + c * 16],
                                        cf[r][c], FL_LDZ, wmma::mem_row_major);
        __syncthreads();

        // dot with leakyrelu — one float4 per lane per 128-chunk
        float4 av = *reinterpret_cast<const float4*>(&att[f0 + lane * 4]);
#pragma unroll
        for (int e = 0; e < 16; e++) {
            int idx = we0 + e;
            float4 vl = *reinterpret_cast<const float4*>(xl + (size_t)s_src[idx] * F + f0 + lane * 4);
            float4 vr = *reinterpret_cast<const float4*>(xr + (size_t)s_dst[idx] * F + f0 + lane * 4);
            float4 vz = *reinterpret_cast<const float4*>(&sz[idx * FL_LDZ + lane * 4]);
            float v0 = vl.x + vr.x + vz.x; v0 = (v0 > 0.0f) ? v0 : NEG_SLOPE * v0;
            float v1 = vl.y + vr.y + vz.y; v1 = (v1 > 0.0f) ? v1 : NEG_SLOPE * v1;
            float v2 = vl.z + vr.z + vz.z; v2 = (v2 > 0.0f) ? v2 : NEG_SLOPE * v2;
            float v3 = vl.w + vr.w + vz.w; v3 = (v3 > 0.0f) ? v3 : NEG_SLOPE * v3;
            acc[e] += v0 * av.x + v1 * av.y + v2 * av.z + v3 * av.w;
        }
        __syncthreads();
    }
#pragma unroll
    for (int e = 0; e < 16; e++) {
        float a = acc[e];
#pragma unroll
        for (int o = 16; o; o >>= 1) a += __shfl_xor_sync(0xffffffffu, a, o);
        if (lane == 0) out_log[tile0 + we0 + e] = a;
    }
}

// ---------------- per-destination softmax + aggregate (+bias+relu) ----------------
template <int NR>
__global__ __launch_bounds__(256) void aggregate(const float* __restrict__ bc,
                                                 float* __restrict__ out, int F) {
    int n = blockIdx.x;
    int tid = threadIdx.x;
    int off = g_off[n];
    int deg = g_off[n + 1] - off;
    __shared__ float red[256];
    __shared__ float s_alpha[128];
    __shared__ int s_src[128];

    float eself = g_eself[n];
    float m = eself;
    for (int j = tid; j < deg; j += 256) m = fmaxf(m, g_elog[off + j]);
    red[tid] = m;
    __syncthreads();
    for (int s = 128; s > 0; s >>= 1) {
        if (tid < s) red[tid] = fmaxf(red[tid], red[tid + s]);
        __syncthreads();
    }
    m = red[0];
    __syncthreads();
    float ds = 0.0f;
    for (int j = tid; j < deg; j += 256) ds += __expf(g_elog[off + j] - m);
    red[tid] = ds;
    __syncthreads();
    for (int s = 128; s > 0; s >>= 1) {
        if (tid < s) red[tid] += red[tid + s];
        __syncthreads();
    }
    float eself_x = __expf(eself - m);
    float inv = 1.0f / (red[0] + eself_x);
    __syncthreads();

    int f0 = tid * NR;
    float acc[NR];
    const float* xln = &g_xl[(size_t)n * F];
    float aself = eself_x * inv;
#pragma unroll
    for (int i = 0; i < NR; i++) acc[i] = aself * xln[f0 + i];

    for (int c0 = 0; c0 < deg; c0 += 128) {
        int cnt = min(128, deg - c0);
        if (tid < cnt) {
            s_alpha[tid] = __expf(g_elog[off + c0 + tid] - m) * inv;
            s_src[tid] = g_ssrc[off + c0 + tid];
        }
        __syncthreads();
        for (int j = 0; j < cnt; j++) {
            const float* xs = &g_xl[(size_t)s_src[j] * F];
            float a = s_alpha[j];
            if (NR == 4) {
                float4 v = *reinterpret_cast<const float4*>(xs + f0);
                acc[0] += a * v.x; acc[1] += a * v.y;
                acc[2] += a * v.z; acc[3] += a * v.w;
            } else if (NR == 2) {
                float2 v = *reinterpret_cast<const float2*>(xs + f0);
                acc[0] += a * v.x; acc[1] += a * v.y;
            } else {
                acc[0] += a * xs[f0];
            }
        }
        __syncthreads();
    }
#pragma unroll
    for (int i = 0; i < NR; i++)
        out[(size_t)n * F + f0 + i] = fmaxf(acc[i] + bc[f0 + i], 0.0f);
}

// ---------------- pooling (batch sorted -> per-graph segment, no atomics) ----------------
__global__ __launch_bounds__(256) void pool_graph(const float* __restrict__ h,
                                                  const int* __restrict__ batch) {
    int g = blockIdx.x;
    int tid = threadIdx.x;
    __shared__ int s_lo, s_hi;
    if (tid == 0) {
        // lower_bound(batch, g) and lower_bound(batch, g+1)
        int lo = 0, hi = N_NODES;
        while (lo < hi) { int mid = (lo + hi) >> 1; if (batch[mid] < g) lo = mid + 1; else hi = mid; }
        s_lo = lo;
        lo = 0; hi = N_NODES;
        while (lo < hi) { int mid = (lo + hi) >> 1; if (batch[mid] < g + 1) lo = mid + 1; else hi = mid; }
        s_hi = lo;
    }
    __syncthreads();
    int lo = s_lo, hi = s_hi;
    float acc = 0.0f;
    for (int n = lo; n < hi; n++) acc += h[(size_t)n * 256 + tid];
    g_pool[g * 256 + tid] = acc / fmaxf((float)(hi - lo), 1.0f);
}

// ---------------- MLP head ----------------
__global__ void fc1_kernel(const float* __restrict__ fc1w, const float* __restrict__ fc1b) {
    int i = blockIdx.x * blockDim.x + threadIdx.x;
    if (i >= NGRAPH * 64) return;
    int g = i >> 6, o = i & 63;
    float s = 0.0f;
    for (int k = 0; k < 256; k++) s += g_pool[g * 256 + k] * fc1w[k * 64 + o];
    g_z[i] = s + fc1b[o];
}

__global__ __launch_bounds__(256) void head_kernel(
    const float* __restrict__ bng, const float* __restrict__ bnb,
    const float* __restrict__ fc2w, const float* __restrict__ fc2b,
    float* __restrict__ out) {
    __shared__ float z[NGRAPH * 64];
    __shared__ float mu[64], iv[64];
    int tid = threadIdx.x;
    for (int i = tid; i < NGRAPH * 64; i += 256) z[i] = g_z[i];
    __syncthreads();
    if (tid < 64) {
        float s = 0.0f, s2 = 0.0f;
        for (int g = 0; g < NGRAPH; g++) {
            float v = z[g * 64 + tid];
            s += v; s2 += v * v;
        }
        float mean = s / (float)NGRAPH;
        float var = s2 / (float)NGRAPH - mean * mean;
        mu[tid] = mean;
        iv[tid] = rsqrtf(var + 1e-5f);
    }
    __syncthreads();
    for (int i = tid; i < NGRAPH * 64; i += 256) {
        int o = i & 63;
        float v = (z[i] - mu[o]) * iv[o] * bng[o] + bnb[o];
        z[i] = fmaxf(v, 0.0f);
    }
    __syncthreads();
    if (tid < NGRAPH) {
        float s = 0.0f;
        for (int o = 0; o < 64; o++) s += z[tid * 64 + o] * fc2w[o];
        out[tid] = s + fc2b[0];
    }
}

static void launch_aggregate(const float* bc, float* hout, int F) {
    if (F == 1024)      aggregate<4><<<N_NODES, 256>>>(bc, hout, F);
    else if (F == 512)  aggregate<2><<<N_NODES, 256>>>(bc, hout, F);
    else                aggregate<1><<<N_NODES, 256>>>(bc, hout, F);
}

// ---------------- host-side layer driver ----------------
static void run_layer(const float* hin, int Fin, int Fout, float* hout,
                      const float* Wl, const float* bl,
                      const float* Wr, const float* br,
                      const float* We, const float* att, const float* bc,
                      const float* edge_attr,
                      float* d_xl, float* d_xr, float* d_loop_attr,
                      float* d_elog, float* d_eself) {
    dim3 t(256);
    dim3 g(Fout / 128, N_NODES / 128);
    gemm_fp16x2_bias<<<g, t, GM_SMEM>>>(hin, Wl, bl, d_xl, N_NODES, Fout, Fin);
    gemm_fp16x2_bias<<<g, t, GM_SMEM>>>(hin, Wr, br, d_xr, N_NODES, Fout, Fin);
    fused_logit<<<N_EDGES / 128, 256, FL_SMEM>>>(edge_attr, We, att, d_xl, d_xr,
                                                 d_elog, Fout, 0);
    fused_logit<<<N_NODES / 128, 256, FL_SMEM>>>(d_loop_attr, We, att, d_xl, d_xr,
                                                 d_eself, Fout, 1);
    launch_aggregate(bc, hout, Fout);
}

extern "C" void kernel_launch(void* const* d_in, const int* in_sizes, int n_in,
                              void* d_out, int out_size) {
    const float* x         = (const float*)d_in[0];
    const int*   ei        = (const int*)d_in[1];
    const float* edge_attr = (const float*)d_in[2];
    const int*   batch     = (const int*)d_in[3];

    const float* Wl[3], *bl[3], *Wr[3], *br[3], *We[3], *att[3], *bc[3];
    for (int l = 0; l < 3; l++) {
        int b = 4 + l * 7;
        Wl[l]  = (const float*)d_in[b + 0];
        bl[l]  = (const float*)d_in[b + 1];
        Wr[l]  = (const float*)d_in[b + 2];
        br[l]  = (const float*)d_in[b + 3];
        We[l]  = (const float*)d_in[b + 4];
        att[l] = (const float*)d_in[b + 5];
        bc[l]  = (const float*)d_in[b + 6];
    }
    const float* fc1w = (const float*)d_in[25];
    const float* fc1b = (const float*)d_in[26];
    const float* bng  = (const float*)d_in[27];
    const float* bnb  = (const float*)d_in[28];
    const float* fc2w = (const float*)d_in[29];
    const float* fc2b = (const float*)d_in[30];
    float* out = (float*)d_out;

    const int* src = ei;
    const int* dst = ei + N_EDGES;

    static bool attr_set = false;
    if (!attr_set) {
        cudaFuncSetAttribute(fused_logit, cudaFuncAttributeMaxDynamicSharedMemorySize, FL_SMEM);
        cudaFuncSetAttribute(gemm_fp16x2_bias, cudaFuncAttributeMaxDynamicSharedMemorySize, GM_SMEM);
        attr_set = true;
    }

    float *d_hA, *d_hB, *d_xl, *d_xr, *d_loop_attr, *d_elog, *d_eself;
    int *d_deg, *d_cur;
    cudaGetSymbolAddress((void**)&d_hA, g_hA);
    cudaGetSymbolAddress((void**)&d_hB, g_hB);
    cudaGetSymbolAddress((void**)&d_xl, g_xl);
    cudaGetSymbolAddress((void**)&d_xr, g_xr);
    cudaGetSymbolAddress((void**)&d_loop_attr, g_loop_attr);
    cudaGetSymbolAddress((void**)&d_elog, g_elog);
    cudaGetSymbolAddress((void**)&d_eself, g_eself);
    cudaGetSymbolAddress((void**)&d_deg, g_deg);
    cudaGetSymbolAddress((void**)&d_cur, g_cur);

    // launches 0-4: preprocessing (independent of the GEMMs)
    zero_i<<<(N_NODES + 255) / 256, 256>>>(d_deg, N_NODES);
    zero_i<<<(N_NODES + 255) / 256, 256>>>(d_cur, N_NODES);
    count_deg<<<(N_EDGES + 255) / 256, 256>>>(dst);
    scan_deg<<<1, 1024>>>();
    scatter_edges<<<(N_EDGES + 255) / 256, 256>>>(src, dst);

    // launch 5: layer-1 xl GEMM (ncu -s 5 profiles this)
    {
        dim3 g(512 / 128, N_NODES / 128);
        gemm_fp16x2_bias<<<g, dim3(256), GM_SMEM>>>(x, Wl[0], bl[0], d_xl, N_NODES, 512, 256);
        gemm_fp16x2_bias<<<g, dim3(256), GM_SMEM>>>(x, Wr[0], br[0], d_xr, N_NODES, 512, 256);
    }
    loop_attr_csr<<<(N_NODES * 32 + 255) / 256, 256>>>(edge_attr);

    // layer 1 (GEMMs already issued)
    fused_logit<<<N_EDGES / 128, 256, FL_SMEM>>>(edge_attr, We[0], att[0], d_xl, d_xr,
                                                 d_elog, 512, 0);
    fused_logit<<<N_NODES / 128, 256, FL_SMEM>>>(d_loop_attr, We[0], att[0], d_xl, d_xr,
                                                 d_eself, 512, 1);
    launch_aggregate(bc[0], d_hA, 512);

    // layers 2, 3
    run_layer(d_hA, 512, 1024, d_hB, Wl[1], bl[1], Wr[1], br[1], We[1], att[1], bc[1],
              edge_attr, d_xl, d_xr, d_loop_attr, d_elog, d_eself);
    run_layer(d_hB, 1024, 256, d_hA, Wl[2], bl[2], Wr[2], br[2], We[2], att[2], bc[2],
              edge_attr, d_xl, d_xr, d_loop_attr, d_elog, d_eself);

    // pool + MLP head
    pool_graph<<<NGRAPH, 256>>>(d_hA, batch);
    fc1_kernel<<<(NGRAPH * 64 + 255) / 256, 256>>>(fc1w, fc1b);
    head_kernel<<<1, 256>>>(bng, bnb, fc2w, fc2b, out);
}